// round 9
// baseline (speedup 1.0000x reference)
#include <cuda_runtime.h>
#include <cuda_fp16.h>
#include <cstdint>

#define N_ROWS 4096
#define VOCAB  50000
#define DIM    64

#define BM 128
#define BN 128
#define TPB   391                 // column tiles per row-block
#define MB    32                  // row blocks
#define GRID_P 296                // 2 CTAs/SM x 148 SMs, all resident

#define ROWB 144                  // bytes per smem tile row (72 halves, conflict-free)
#define TILE_SM (BM * ROWB)       // 18432
#define SMEM_TOTAL (4 * TILE_SM)  // A0,A1,B0,B1 = 73728

#define LOG2E 1.4426950408889634f

// scratch (no allocs allowed -> device globals)
__device__ float  g_sums[N_ROWS];
__device__ float  g_loss;
__device__ int    g_loss_cnt;
__device__ int    g_done[MB];
__device__ __half g_A16[N_ROWS * DIM];   // pre-scaled by log2e
__device__ __half g_B16[VOCAB * DIM];

__device__ __forceinline__ uint32_t smem_u32(const void* p) {
    uint32_t a;
    asm("{ .reg .u64 t; cvta.to.shared.u64 t, %1; cvt.u32.u64 %0, t; }" : "=r"(a) : "l"(p));
    return a;
}
__device__ __forceinline__ float ex2f(float x) {
    float y;
    asm("ex2.approx.f32 %0, %1;" : "=f"(y) : "f"(x));
    return y;
}
__device__ __forceinline__ int ld_acq(const int* p) {
    int v;
    asm volatile("ld.acquire.gpu.b32 %0, [%1];" : "=r"(v) : "l"(p) : "memory");
    return v;
}
// B-tile column permutation: smem MMA-space row q = nf*8+lc*2+j holds natural
// column (nf&2)*8 + lc*4 + (nf&1)*2 + j  -> pass-1 stores are full STG.128.
__device__ __forceinline__ int permB(int r) {
    int q = r & 31;
    int nf = q >> 3, lc = (q >> 1) & 3, j = q & 1;
    return (r & ~31) | ((nf & 2) << 3) | (lc << 2) | ((nf & 1) << 1) | j;
}
#define CP_ASYNC16(dst, src, sz) \
    asm volatile("cp.async.cg.shared.global [%0], [%1], 16, %2;" :: "r"(dst), "l"(src), "r"(sz))
#define CP_COMMIT()  asm volatile("cp.async.commit_group;" ::: "memory")
#define CP_WAIT0()   asm volatile("cp.async.wait_group 0;" ::: "memory")
#define LDMATRIX_X4(r0, r1, r2, r3, addr) \
    asm volatile("ldmatrix.sync.aligned.m8n8.x4.shared.b16 {%0,%1,%2,%3}, [%4];" \
                 : "=r"(r0), "=r"(r1), "=r"(r2), "=r"(r3) : "r"(addr))

// tile ownership of block mm for CTA b: rotating (gcd(95,296)=1 -> balanced)
__device__ __forceinline__ int tiles_of(int b, int mm, int* t) {
    int t0 = (b + 95 * mm) % 296;
    t[0] = t0;
    if (t0 <= TPB - 1 - 296) { t[1] = t0 + 296; return 2; }
    return 1;
}
__device__ __forceinline__ bool first_of_iter(int b, int mm, int* v0) {
    int t[2];
    if (mm < MB)  { tiles_of(b, mm, t);     *v0 = t[0] * BN; return true; }
    if (mm == MB) { tiles_of(b, MB - 1, t); *v0 = t[0] * BN; return true; }
    return false;
}

// init + fp32 -> fp16 convert. A pre-scaled by log2e so exp(logit) == ex2(gemm_out).
__global__ void convert_kernel(const float* __restrict__ A, const float* __restrict__ B) {
    int i = blockIdx.x * blockDim.x + threadIdx.x;
    if (i < N_ROWS) g_sums[i] = 0.f;
    if (i < MB) g_done[i] = 0;
    if (i == 0) { g_loss = 0.f; g_loss_cnt = 0; }
    const int nA4 = N_ROWS * DIM / 4;
    const int nB4 = VOCAB * DIM / 4;
    if (i < nA4) {
        float4 v = ((const float4*)A)[i];
        __half2* d = (__half2*)g_A16;
        d[i * 2 + 0] = __floats2half2_rn(v.x * LOG2E, v.y * LOG2E);
        d[i * 2 + 1] = __floats2half2_rn(v.z * LOG2E, v.w * LOG2E);
    }
    int j = i - nA4;
    if (j >= 0 && j < nB4) {
        float4 v = ((const float4*)B)[j];
        __half2* d = (__half2*)g_B16;
        d[j * 2 + 0] = __floats2half2_rn(v.x, v.y);
        d[j * 2 + 1] = __floats2half2_rn(v.z, v.w);
    }
}

// Fused persistent kernel: per iteration m -> pass0 tiles of block m (GEMM->ex2->sums),
// signal; spin done[m-1]; loss for block m-1 (one CTA); pass1 tiles of block m-1
// (GEMM->ex2*inv->STG.128 streaming). Pass0 compute overlaps pass1 DRAM chip-wide.
__global__ void __launch_bounds__(256, 2)
fused_kernel(float* __restrict__ out,
             const int* __restrict__ label_words,
             const float* __restrict__ inp,
             const float* __restrict__ emb,
             long long lossIdx)
{
    extern __shared__ char smem[];
    __shared__ float lred[256];
    const uint32_t sbase = smem_u32(smem);
    const uint32_t sB0 = sbase + 2 * TILE_SM;

    const int tid  = threadIdx.x;
    const int lane = tid & 31;
    const int wid  = tid >> 5;
    const int wm = wid >> 2, wn = wid & 3;
    const int mBase = wm * 64, nBase = wn * 32;
    const int lr = lane >> 2, lc = lane & 3;
    const int b = blockIdx.x;

    // per-lane ldmatrix offsets (within a tile buffer)
    const uint32_t aOff =
        (uint32_t)(mBase + ((lane >> 3) & 1) * 8 + (lane & 7)) * ROWB + (lane >> 4) * 16;
    const uint32_t bOff =
        (uint32_t)(nBase + (lane >> 4) * 8 + (lane & 7)) * ROWB + ((lane >> 3) & 1) * 16;

    // prefetch helper target: full-thread, 4x16B per thread
    auto prefetchB = [&](int v0, uint32_t dstBase) {
        #pragma unroll
        for (int t = 0; t < 4; t++) {
            int i = tid + t * 256;
            int row = i >> 3, c8 = i & 7;
            int v = v0 + permB(row);
            uint32_t dst = dstBase + row * ROWB + c8 * 16;
            const __half* src = g_B16 + (size_t)v * DIM + c8 * 8;
            CP_ASYNC16(dst, src, (v < VOCAB) ? 16 : 0);
        }
        CP_COMMIT();
    };

    // prologue: prefetch very first tile
    {
        int v0;
        first_of_iter(b, 0, &v0);
        prefetchB(v0, sB0);
    }

    int bbuf = 0;
    float rr[8];                                   // racc (p0) / rinv (p1) — disjoint lifetimes
    #pragma unroll
    for (int k = 0; k < 8; k++) rr[k] = 0.f;

    for (int m = 0; m <= MB; m++) {
        int tP0[2], tP1[2];
        const int nP0 = (m < MB) ? tiles_of(b, m, tP0) : 0;
        const int nP1 = (m >= 1) ? tiles_of(b, m - 1, tP1) : 0;
        const int m0  = m * BM;
        const int m1  = (m - 1) * BM;

        // load A(m) into buffer m&1 (its previous tenant A(m-2) was last read in iter m-1)
        if (m < MB) {
            __syncthreads();
            char* Ad = smem + (m & 1) * TILE_SM;
            const uint4* Ag = (const uint4*)(g_A16 + (size_t)m0 * DIM);
            #pragma unroll
            for (int t = 0; t < 4; t++) {
                int i = tid + t * 256;
                int row = i >> 3, c8 = i & 7;
                *(uint4*)(Ad + row * ROWB + c8 * 16) = Ag[i];
            }
        }

        // ================= pass-0 segment: block m =================
        for (int it = 0; it < nP0; it++) {
            const int v0 = tP0[it] * BN;
            int nxt; bool hasNext = true;
            if (it + 1 < nP0) nxt = tP0[it + 1] * BN;
            else if (nP1 > 0) nxt = tP1[0] * BN;
            else hasNext = first_of_iter(b, m + 1, &nxt);

            CP_WAIT0();
            __syncthreads();
            if (hasNext) prefetchB(nxt, sB0 + (bbuf ^ 1) * TILE_SM);

            const uint32_t aAddr0 = sbase + (m & 1) * TILE_SM + aOff;
            const uint32_t bAddr0 = sB0 + bbuf * TILE_SM + bOff;
            float c[4][4][4];
            #pragma unroll
            for (int a = 0; a < 4; a++)
                #pragma unroll
                for (int bb = 0; bb < 4; bb++)
                    #pragma unroll
                    for (int d = 0; d < 4; d++) c[a][bb][d] = 0.f;
            #pragma unroll
            for (int kk = 0; kk < 4; kk++) {
                unsigned af[4][4], bf[4][2];
                #pragma unroll
                for (int mf = 0; mf < 4; mf++)
                    LDMATRIX_X4(af[mf][0], af[mf][1], af[mf][2], af[mf][3],
                                aAddr0 + mf * (16 * ROWB) + kk * 32);
                #pragma unroll
                for (int p = 0; p < 2; p++)
                    LDMATRIX_X4(bf[2 * p][0], bf[2 * p][1], bf[2 * p + 1][0], bf[2 * p + 1][1],
                                bAddr0 + p * (16 * ROWB) + kk * 32);
                #pragma unroll
                for (int mf = 0; mf < 4; mf++)
                    #pragma unroll
                    for (int nf = 0; nf < 4; nf++) {
                        asm volatile(
                            "mma.sync.aligned.m16n8k16.row.col.f32.f16.f16.f32 "
                            "{%0,%1,%2,%3}, {%4,%5,%6,%7}, {%8,%9}, {%0,%1,%2,%3};"
                            : "+f"(c[mf][nf][0]), "+f"(c[mf][nf][1]),
                              "+f"(c[mf][nf][2]), "+f"(c[mf][nf][3])
                            : "r"(af[mf][0]), "r"(af[mf][1]), "r"(af[mf][2]), "r"(af[mf][3]),
                              "r"(bf[nf][0]), "r"(bf[nf][1]));
                    }
            }
            const bool full = (v0 + BN <= VOCAB);
            if (full) {
                #pragma unroll
                for (int mf = 0; mf < 4; mf++)
                    #pragma unroll
                    for (int h = 0; h < 2; h++) {
                        __half2 hs = __floats2half2_rn(0.f, 0.f);
                        #pragma unroll
                        for (int nf = 0; nf < 4; nf++) {
                            __half2 p = __floats2half2_rn(c[mf][nf][h * 2 + 0],
                                                          c[mf][nf][h * 2 + 1]);
                            hs = __hadd2(hs, h2exp2(p));
                        }
                        float2 f = __half22float2(hs);
                        rr[mf * 2 + h] += f.x + f.y;
                    }
            } else {
                #pragma unroll
                for (int mf = 0; mf < 4; mf++)
                    #pragma unroll
                    for (int h = 0; h < 2; h++) {
                        float s = 0.f;
                        #pragma unroll
                        for (int nf = 0; nf < 4; nf++) {
                            int col = v0 + nBase + (nf >> 1) * 16 + lc * 4 + (nf & 1) * 2;
                            float e0 = ex2f(c[mf][nf][h * 2 + 0]);
                            float e1 = ex2f(c[mf][nf][h * 2 + 1]);
                            s += (col     < VOCAB) ? e0 : 0.f;
                            s += (col + 1 < VOCAB) ? e1 : 0.f;
                        }
                        rr[mf * 2 + h] += s;
                    }
            }
            bbuf ^= 1;
        }

        // flush block-m sums, release-signal done[m]
        if (m < MB) {
            #pragma unroll
            for (int k = 0; k < 8; k++) {
                float s = rr[k];
                s += __shfl_xor_sync(0xffffffffu, s, 1);
                s += __shfl_xor_sync(0xffffffffu, s, 2);
                if (lc == 0)
                    atomicAdd(&g_sums[m0 + mBase + (k >> 1) * 16 + (k & 1) * 8 + lr], s);
                rr[k] = 0.f;
            }
            __threadfence();
            __syncthreads();
            if (tid == 0) atomicAdd(&g_done[m], 1);
        }

        // ================= pass-1 segment: block m-1 =================
        if (m >= 1) {
            const int mm = m - 1;
            if (tid == 0) {
                while (ld_acq(&g_done[mm]) < GRID_P) __nanosleep(32);
            }
            __syncthreads();

            // fused loss for block mm (one CTA; sums for block mm are final)
            if (b == mm) {
                bool is64 = true;
                #pragma unroll
                for (int i = 0; i < 64; i++) is64 &= (label_words[2 * i + 1] == 0);
                int r = mm * BM + (tid >> 1);
                int half = tid & 1;
                int lab = is64 ? label_words[2 * r] : label_words[r];
                const float4* a4 = (const float4*)(inp + (size_t)r * DIM + half * 32);
                const float4* b4 = (const float4*)(emb + (size_t)lab * DIM + half * 32);
                float dot = 0.f;
                #pragma unroll
                for (int i = 0; i < 8; i++) {
                    float4 x = a4[i], y = b4[i];
                    dot += x.x * y.x + x.y * y.y + x.z * y.z + x.w * y.w;
                }
                dot += __shfl_xor_sync(0xffffffffu, dot, 1);
                lred[tid] = (half == 0) ? (logf(__ldcg(&g_sums[r])) - dot) : 0.f;
                __syncthreads();
                for (int s = 128; s > 0; s >>= 1) {
                    if (tid < s) lred[tid] += lred[tid + s];
                    __syncthreads();
                }
                if (tid == 0) {
                    atomicAdd(&g_loss, lred[0]);
                    __threadfence();
                    int c = atomicAdd(&g_loss_cnt, 1);
                    if (c == MB - 1)
                        out[lossIdx] = atomicAdd(&g_loss, 0.f) * (1.0f / (float)N_ROWS);
                }
            }

            #pragma unroll
            for (int k = 0; k < 8; k++)
                rr[k] = 1.0f / __ldcg(&g_sums[m1 + mBase + (k >> 1) * 16 + (k & 1) * 8 + lr]);

            for (int it = 0; it < nP1; it++) {
                const int v0 = tP1[it] * BN;
                int nxt; bool hasNext = true;
                if (it + 1 < nP1) nxt = tP1[it + 1] * BN;
                else hasNext = first_of_iter(b, m + 1, &nxt);

                CP_WAIT0();
                __syncthreads();
                if (hasNext) prefetchB(nxt, sB0 + (bbuf ^ 1) * TILE_SM);

                const uint32_t aAddr0 = sbase + (mm & 1) * TILE_SM + aOff;
                const uint32_t bAddr0 = sB0 + bbuf * TILE_SM + bOff;
                float c[4][4][4];
                #pragma unroll
                for (int a = 0; a < 4; a++)
                    #pragma unroll
                    for (int bb = 0; bb < 4; bb++)
                        #pragma unroll
                        for (int d = 0; d < 4; d++) c[a][bb][d] = 0.f;
                #pragma unroll
                for (int kk = 0; kk < 4; kk++) {
                    unsigned af[4][4], bf[4][2];
                    #pragma unroll
                    for (int mf = 0; mf < 4; mf++)
                        LDMATRIX_X4(af[mf][0], af[mf][1], af[mf][2], af[mf][3],
                                    aAddr0 + mf * (16 * ROWB) + kk * 32);
                    #pragma unroll
                    for (int p = 0; p < 2; p++)
                        LDMATRIX_X4(bf[2 * p][0], bf[2 * p][1], bf[2 * p + 1][0], bf[2 * p + 1][1],
                                    bAddr0 + p * (16 * ROWB) + kk * 32);
                    #pragma unroll
                    for (int mf = 0; mf < 4; mf++)
                        #pragma unroll
                        for (int nf = 0; nf < 4; nf++) {
                            asm volatile(
                                "mma.sync.aligned.m16n8k16.row.col.f32.f16.f16.f32 "
                                "{%0,%1,%2,%3}, {%4,%5,%6,%7}, {%8,%9}, {%0,%1,%2,%3};"
                                : "+f"(c[mf][nf][0]), "+f"(c[mf][nf][1]),
                                  "+f"(c[mf][nf][2]), "+f"(c[mf][nf][3])
                                : "r"(af[mf][0]), "r"(af[mf][1]), "r"(af[mf][2]), "r"(af[mf][3]),
                                  "r"(bf[nf][0]), "r"(bf[nf][1]));
                        }
                }
                const bool full = (v0 + BN <= VOCAB);
                #pragma unroll
                for (int mf = 0; mf < 4; mf++) {
                    #pragma unroll
                    for (int h = 0; h < 2; h++) {
                        const float r = rr[mf * 2 + h];
                        const int rl = mBase + mf * 16 + h * 8 + lr;
                        float* op = out + (size_t)(m1 + rl) * VOCAB;
                        #pragma unroll
                        for (int gg = 0; gg < 2; gg++) {
                            int col = v0 + nBase + gg * 16 + lc * 4;
                            if (full || col < VOCAB) {   // 50000 % 4 == 0 -> no straddle
                                float4 p;
                                p.x = ex2f(c[mf][2 * gg + 0][h * 2 + 0]) * r;
                                p.y = ex2f(c[mf][2 * gg + 0][h * 2 + 1]) * r;
                                p.z = ex2f(c[mf][2 * gg + 1][h * 2 + 0]) * r;
                                p.w = ex2f(c[mf][2 * gg + 1][h * 2 + 1]) * r;
                                __stcs((float4*)(op + col), p);
                            }
                        }
                    }
                }
                bbuf ^= 1;
            }
        }
    }
}

extern "C" void kernel_launch(void* const* d_in, const int* in_sizes, int n_in,
                              void* d_out, int out_size) {
    const int*   label = (const int*)d_in[0];      // int32 or int64 (sniffed in-kernel)
    const float* inp   = (const float*)d_in[1];    // [4096, 64]
    const float* emb   = (const float*)d_in[2];    // [50000, 64]
    float* out = (float*)d_out;                    // [4096*50000] probs + [1] loss

    static int attr_done = 0;
    if (!attr_done) {
        cudaFuncSetAttribute(fused_kernel,
                             cudaFuncAttributeMaxDynamicSharedMemorySize, SMEM_TOTAL);
        attr_done = 1;
    }
    long long lossIdx = (long long)out_size - 1;

    convert_kernel<<<(N_ROWS * DIM / 4 + VOCAB * DIM / 4 + 255) / 256, 256>>>(inp, emb);
    fused_kernel<<<GRID_P, 256, SMEM_TOTAL>>>(out, label, inp, emb, lossIdx);
}

// round 10
// speedup vs baseline: 1.6258x; 1.6258x over previous
#include <cuda_runtime.h>
#include <cuda_fp16.h>
#include <cstdint>

#define N_ROWS 4096
#define VOCAB  50000
#define DIM    64

#define BM 128
#define BN 128
#define TPB   391                 // column tiles per row-block
#define MB    32                  // row blocks
#define TOTAL (TPB * MB)          // 12512
#define GRID_P 444                // 3 CTAs/SM x 148 SMs
#define LOSS_BLOCKS 16

#define ROWB 144                  // bytes per smem tile row (72 halves, conflict-free)
#define A_SM_BYTES (BM * ROWB)    // 18432
#define SMEM_TOTAL (3 * A_SM_BYTES)   // A + B double buffer = 55296 (x3 CTAs = 162KB/SM)

#define LOG2E 1.4426950408889634f

// scratch (no allocs allowed -> device globals)
__device__ float  g_sums[N_ROWS];
__device__ float  g_loss;
__device__ int    g_loss_cnt;
__device__ __half g_A16[N_ROWS * DIM];   // pre-scaled by log2e
__device__ __half g_B16[VOCAB * DIM];

__device__ __forceinline__ uint32_t smem_u32(const void* p) {
    uint32_t a;
    asm("{ .reg .u64 t; cvta.to.shared.u64 t, %1; cvt.u32.u64 %0, t; }" : "=r"(a) : "l"(p));
    return a;
}
__device__ __forceinline__ float ex2f(float x) {      // exp(logit): logits are log2-domain
    float y;
    asm("ex2.approx.f32 %0, %1;" : "=f"(y) : "f"(x));
    return y;
}
// B-tile column permutation: smem MMA-space row q = nf*8+lc*2+j holds natural
// column (nf&2)*8 + lc*4 + (nf&1)*2 + j  -> pass-1 stores are full STG.128.
__device__ __forceinline__ int permB(int r) {
    int q = r & 31;
    int nf = q >> 3, lc = (q >> 1) & 3, j = q & 1;
    return (r & ~31) | ((nf & 2) << 3) | (lc << 2) | ((nf & 1) << 1) | j;
}
#define CP_ASYNC16(dst, src, sz) \
    asm volatile("cp.async.cg.shared.global [%0], [%1], 16, %2;" :: "r"(dst), "l"(src), "r"(sz))
#define CP_COMMIT()  asm volatile("cp.async.commit_group;" ::: "memory")
#define CP_WAIT0()   asm volatile("cp.async.wait_group 0;" ::: "memory")
#define LDMATRIX_X4(r0, r1, r2, r3, addr) \
    asm volatile("ldmatrix.sync.aligned.m8n8.x4.shared.b16 {%0,%1,%2,%3}, [%4];" \
                 : "=r"(r0), "=r"(r1), "=r"(r2), "=r"(r3) : "r"(addr))

// init + fp32 -> fp16 convert. A is pre-scaled by log2e so exp(logit) == ex2(gemm_out).
__global__ void convert_kernel(const float* __restrict__ A, const float* __restrict__ B) {
    int i = blockIdx.x * blockDim.x + threadIdx.x;               // float4 index
    if (i < N_ROWS) g_sums[i] = 0.f;
    if (i == 0) { g_loss = 0.f; g_loss_cnt = 0; }
    const int nA4 = N_ROWS * DIM / 4;
    const int nB4 = VOCAB * DIM / 4;
    if (i < nA4) {
        float4 v = ((const float4*)A)[i];
        __half2* d = (__half2*)g_A16;
        d[i * 2 + 0] = __floats2half2_rn(v.x * LOG2E, v.y * LOG2E);
        d[i * 2 + 1] = __floats2half2_rn(v.z * LOG2E, v.w * LOG2E);
    }
    int j = i - nA4;
    if (j >= 0 && j < nB4) {
        float4 v = ((const float4*)B)[j];
        __half2* d = (__half2*)g_B16;
        d[j * 2 + 0] = __floats2half2_rn(v.x, v.y);
        d[j * 2 + 1] = __floats2half2_rn(v.z, v.w);
    }
}

// Persistent strip kernel; contiguous tiles per CTA; cp.async double-buffered B.
// mf-major schedule: per 16-row slab -> 16 MMAs then that slab's epilogue, so
// stores/exp interleave with tensor work inside each warp.
// PASS 0: logits -> ex2 (f16x2) -> row-sum register accum -> atomic flush per m.
// PASS 1: loss (blocks 0..15) then logits -> ex2 * (1/sum) -> STG.128 streaming.
template <int PASS>
__global__ void __launch_bounds__(256, 3)
gemm_softmax_kernel(float* __restrict__ out,
                    const int* __restrict__ label_words,
                    const float* __restrict__ inp,
                    const float* __restrict__ emb,
                    long long lossIdx)
{
    extern __shared__ char smem[];
    __half* As = (__half*)smem;
    const uint32_t sA = smem_u32(smem);
    const uint32_t sB0 = sA + A_SM_BYTES;

    const int tid  = threadIdx.x;
    const int lane = tid & 31;
    const int wid  = tid >> 5;
    const int wm = wid >> 2, wn = wid & 3;
    const int mBase = wm * 64, nBase = wn * 32;
    const int lr = lane >> 2, lc = lane & 3;

    // ldmatrix per-lane base addresses (kk=0, mf/p=0)
    const uint32_t aAddr0 = sA +
        (uint32_t)(mBase + ((lane >> 3) & 1) * 8 + (lane & 7)) * ROWB + (lane >> 4) * 16;
    const uint32_t bOff0 =
        (uint32_t)(nBase + (lane >> 4) * 8 + (lane & 7)) * ROWB + ((lane >> 3) & 1) * 16;

    // balanced contiguous strips; remainder tiles go to HIGH block ids so the
    // loss blocks (0..15) get the short strips
    const int base = TOTAL / GRID_P, rem = TOTAL % GRID_P;
    const int b = blockIdx.x;
    const int cut = GRID_P - rem;
    const int gBeg = b * base + (b > cut ? b - cut : 0);
    const int gEnd = gBeg + base + (b >= cut ? 1 : 0);

    // prologue: prefetch first B tile into buffer 0 (async; overlaps loss below)
    {
        const int v0 = (gBeg % TPB) * BN;
        #pragma unroll
        for (int t = 0; t < 4; t++) {
            int i = tid + t * 256;                 // 16B chunk id, 0..1023
            int row = i >> 3, c8 = i & 7;
            int v = v0 + permB(row);
            uint32_t dst = sB0 + row * ROWB + c8 * 16;
            const __half* src = g_B16 + (size_t)v * DIM + c8 * 8;
            CP_ASYNC16(dst, src, (v < VOCAB) ? 16 : 0);
        }
        CP_COMMIT();
    }

    // ---- fused loss (PASS 1, blocks 0..15): sums are final before this kernel ----
    if (PASS == 1 && b < LOSS_BLOCKS) {
        int n = b * 256 + tid;
        bool is64 = true;                          // int64 labels: odd words all zero
        #pragma unroll
        for (int i = 0; i < 64; i++) is64 &= (label_words[2 * i + 1] == 0);
        int lab = is64 ? label_words[2 * n] : label_words[n];
        const float4* a4 = (const float4*)(inp + (size_t)n * DIM);
        const float4* b4 = (const float4*)(emb + (size_t)lab * DIM);
        float dot = 0.f;
        #pragma unroll
        for (int i = 0; i < DIM / 4; i++) {
            float4 x = a4[i], y = b4[i];
            dot += x.x * y.x + x.y * y.y + x.z * y.z + x.w * y.w;
        }
        float v = logf(g_sums[n]) - dot;
        float* red = (float*)smem;                 // A region; A not loaded yet
        red[tid] = v;
        __syncthreads();
        for (int s = 128; s > 0; s >>= 1) {
            if (tid < s) red[tid] += red[tid + s];
            __syncthreads();
        }
        if (tid == 0) {
            atomicAdd(&g_loss, red[0]);
            __threadfence();
            int c = atomicAdd(&g_loss_cnt, 1);
            if (c == LOSS_BLOCKS - 1)
                out[lossIdx] = atomicAdd(&g_loss, 0.f) * (1.0f / (float)N_ROWS);
        }
    }

    int curM = -1;
    int buf = 0;
    float racc[8];                                 // pass0 row-sum accumulators
    float rinv[8];                                 // pass1 reciprocal sums
    #pragma unroll
    for (int k = 0; k < 8; k++) { racc[k] = 0.f; rinv[k] = 0.f; }

    for (int g = gBeg; g < gEnd; g++) {
        const int m = g / TPB;
        const int v0 = (g % TPB) * BN;
        const int m0 = m * BM;

        if (m != curM) {                           // <=2 times per strip
            __syncthreads();                       // everyone done with old As
            if (PASS == 0 && curM >= 0) {          // flush row sums of previous block
                #pragma unroll
                for (int k = 0; k < 8; k++) {
                    float s = racc[k];
                    s += __shfl_xor_sync(0xffffffffu, s, 1);
                    s += __shfl_xor_sync(0xffffffffu, s, 2);
                    if (lc == 0)
                        atomicAdd(&g_sums[curM * BM + mBase + (k >> 1) * 16 + (k & 1) * 8 + lr], s);
                    racc[k] = 0.f;
                }
            }
            const uint4* Ag = (const uint4*)(g_A16 + (size_t)m0 * DIM);
            #pragma unroll
            for (int t = 0; t < 4; t++) {
                int i = tid + t * 256;
                int row = i >> 3, c8 = i & 7;
                *(uint4*)((char*)As + row * ROWB + c8 * 16) = Ag[i];
            }
            if (PASS == 1) {
                #pragma unroll
                for (int k = 0; k < 8; k++)
                    rinv[k] = 1.0f / __ldcg(&g_sums[m0 + mBase + (k >> 1) * 16 + (k & 1) * 8 + lr]);
            }
            curM = m;
        }

        CP_WAIT0();                                // current B buffer landed
        __syncthreads();

        // prefetch next B tile into the other buffer (overlaps MMA + epilogue)
        if (g + 1 < gEnd) {
            const int vn = ((g + 1) % TPB) * BN;
            const uint32_t sBn = sB0 + (buf ^ 1) * A_SM_BYTES;
            #pragma unroll
            for (int t = 0; t < 4; t++) {
                int i = tid + t * 256;
                int row = i >> 3, c8 = i & 7;
                int v = vn + permB(row);
                uint32_t dst = sBn + row * ROWB + c8 * 16;
                const __half* src = g_B16 + (size_t)v * DIM + c8 * 8;
                CP_ASYNC16(dst, src, (v < VOCAB) ? 16 : 0);
            }
            CP_COMMIT();
        }

        // ---- preload ALL B fragments (32 regs), then mf-major slabs ----
        const uint32_t bAddr0 = sB0 + buf * A_SM_BYTES + bOff0;
        unsigned bf[4][4][2];                      // [kk][nf][2]
        #pragma unroll
        for (int kk = 0; kk < 4; kk++)
            #pragma unroll
            for (int p = 0; p < 2; p++)
                LDMATRIX_X4(bf[kk][2 * p][0], bf[kk][2 * p][1],
                            bf[kk][2 * p + 1][0], bf[kk][2 * p + 1][1],
                            bAddr0 + p * (16 * ROWB) + kk * 32);

        const bool full = (v0 + BN <= VOCAB);
        #pragma unroll
        for (int mf = 0; mf < 4; mf++) {
            float c[4][4];
            #pragma unroll
            for (int nf = 0; nf < 4; nf++)
                #pragma unroll
                for (int d = 0; d < 4; d++) c[nf][d] = 0.f;
            #pragma unroll
            for (int kk = 0; kk < 4; kk++) {
                unsigned a0, a1, a2, a3;
                LDMATRIX_X4(a0, a1, a2, a3, aAddr0 + mf * (16 * ROWB) + kk * 32);
                #pragma unroll
                for (int nf = 0; nf < 4; nf++) {
                    asm volatile(
                        "mma.sync.aligned.m16n8k16.row.col.f32.f16.f16.f32 "
                        "{%0,%1,%2,%3}, {%4,%5,%6,%7}, {%8,%9}, {%0,%1,%2,%3};"
                        : "+f"(c[nf][0]), "+f"(c[nf][1]), "+f"(c[nf][2]), "+f"(c[nf][3])
                        : "r"(a0), "r"(a1), "r"(a2), "r"(a3),
                          "r"(bf[kk][nf][0]), "r"(bf[kk][nf][1]));
                }
            }
            // ---- slab epilogue (interleaves with next slab's MMAs) ----
            if (PASS == 0) {
                if (full) {
                    #pragma unroll
                    for (int h = 0; h < 2; h++) {
                        __half2 hs = __floats2half2_rn(0.f, 0.f);
                        #pragma unroll
                        for (int nf = 0; nf < 4; nf++) {
                            __half2 p = __floats2half2_rn(c[nf][h * 2 + 0], c[nf][h * 2 + 1]);
                            hs = __hadd2(hs, h2exp2(p));   // ex2.approx.f16x2
                        }
                        float2 f = __half22float2(hs);
                        racc[mf * 2 + h] += f.x + f.y;
                    }
                } else {                           // 32 of 12512 tiles: masked scalar path
                    #pragma unroll
                    for (int h = 0; h < 2; h++) {
                        float s = 0.f;
                        #pragma unroll
                        for (int nf = 0; nf < 4; nf++) {
                            int col = v0 + nBase + (nf >> 1) * 16 + lc * 4 + (nf & 1) * 2;
                            float e0 = ex2f(c[nf][h * 2 + 0]);
                            float e1 = ex2f(c[nf][h * 2 + 1]);
                            s += (col     < VOCAB) ? e0 : 0.f;
                            s += (col + 1 < VOCAB) ? e1 : 0.f;
                        }
                        racc[mf * 2 + h] += s;
                    }
                }
            } else {
                #pragma unroll
                for (int h = 0; h < 2; h++) {
                    const float r = rinv[mf * 2 + h];
                    const int rl = mBase + mf * 16 + h * 8 + lr;
                    float* op = out + (size_t)(m0 + rl) * VOCAB;
                    #pragma unroll
                    for (int gg = 0; gg < 2; gg++) {
                        int col = v0 + nBase + gg * 16 + lc * 4;
                        if (full || col < VOCAB) {   // 50000 % 4 == 0 -> no straddle
                            float4 p;
                            p.x = ex2f(c[2 * gg + 0][h * 2 + 0]) * r;
                            p.y = ex2f(c[2 * gg + 0][h * 2 + 1]) * r;
                            p.z = ex2f(c[2 * gg + 1][h * 2 + 0]) * r;
                            p.w = ex2f(c[2 * gg + 1][h * 2 + 1]) * r;
                            __stcs((float4*)(op + col), p);
                        }
                    }
                }
            }
        }
        buf ^= 1;
    }

    if (PASS == 0 && curM >= 0) {                  // final flush
        #pragma unroll
        for (int k = 0; k < 8; k++) {
            float s = racc[k];
            s += __shfl_xor_sync(0xffffffffu, s, 1);
            s += __shfl_xor_sync(0xffffffffu, s, 2);
            if (lc == 0)
                atomicAdd(&g_sums[curM * BM + mBase + (k >> 1) * 16 + (k & 1) * 8 + lr], s);
        }
    }
}

extern "C" void kernel_launch(void* const* d_in, const int* in_sizes, int n_in,
                              void* d_out, int out_size) {
    const int*   label = (const int*)d_in[0];      // int32 or int64 (sniffed in-kernel)
    const float* inp   = (const float*)d_in[1];    // [4096, 64]
    const float* emb   = (const float*)d_in[2];    // [50000, 64]
    float* out = (float*)d_out;                    // [4096*50000] probs + [1] loss

    static int attr_done = 0;
    if (!attr_done) {
        cudaFuncSetAttribute(gemm_softmax_kernel<0>,
                             cudaFuncAttributeMaxDynamicSharedMemorySize, SMEM_TOTAL);
        cudaFuncSetAttribute(gemm_softmax_kernel<1>,
                             cudaFuncAttributeMaxDynamicSharedMemorySize, SMEM_TOTAL);
        attr_done = 1;
    }
    long long lossIdx = (long long)out_size - 1;

    convert_kernel<<<(N_ROWS * DIM / 4 + VOCAB * DIM / 4 + 255) / 256, 256>>>(inp, emb);
    gemm_softmax_kernel<0><<<GRID_P, 256, SMEM_TOTAL>>>(out, label, inp, emb, lossIdx);
    gemm_softmax_kernel<1><<<GRID_P, 256, SMEM_TOTAL>>>(out, label, inp, emb, lossIdx);
}